// round 1
// baseline (speedup 1.0000x reference)
#include <cuda_runtime.h>
#include <math.h>

#define BB 8
#define NN 4096

static __device__ __constant__ float kEPS  = 1e-5f;
static __device__ __constant__ float kFACT = 2.0f;

// Scratch (device globals; no allocation allowed)
__device__ float g_pcn[BB][3][NN];
__device__ float g_dist[BB][NN];

// ---------------------------------------------------------------------------
// Kernel 1: per (b, n) row — min-distance pass, softmax pass, pc_nearest, dist
// ---------------------------------------------------------------------------
__global__ void __launch_bounds__(256, 3)
cpnet_rows(const float* __restrict__ pc1, const float* __restrict__ pc2) {
    extern __shared__ float4 sk[];  // pc2[b] transposed: 4096 x float4 = 64KB
    const int b = blockIdx.y;
    const float* p2 = pc2 + (size_t)b * 4 * NN;
    const float* p1 = pc1 + (size_t)b * 4 * NN;

    for (int i = threadIdx.x; i < NN; i += blockDim.x) {
        sk[i] = make_float4(p2[i], p2[NN + i], p2[2 * NN + i], p2[3 * NN + i]);
    }
    __syncthreads();

    const int warp = threadIdx.x >> 5;
    const int lane = threadIdx.x & 31;

    for (int r = 0; r < 4; ++r) {
        const int n = blockIdx.x * 32 + r * 8 + warp;
        const float x1 = p1[n];
        const float y1 = p1[NN + n];
        const float z1 = p1[2 * NN + n];
        const float w1 = p1[3 * NN + n];

        // Pass 1: min squared distance -> softmax max
        float dmin = 3.4e38f;
        #pragma unroll 4
        for (int m = lane; m < NN; m += 32) {
            float4 k = sk[m];
            float dx = x1 - k.x, dy = y1 - k.y, dz = z1 - k.z;
            float d = fmaf(dx, dx, fmaf(dy, dy, dz * dz));
            dmin = fminf(dmin, d);
        }
        #pragma unroll
        for (int o = 16; o; o >>= 1)
            dmin = fminf(dmin, __shfl_xor_sync(0xffffffffu, dmin, o));
        const float smax = __fdividef(kFACT, fmaxf(dmin, kEPS));

        // Pass 2: exp weights + weighted accumulation
        float Z = 0.f, a0 = 0.f, a1 = 0.f, a2 = 0.f, a3 = 0.f;
        #pragma unroll 4
        for (int m = lane; m < NN; m += 32) {
            float4 k = sk[m];
            float dx = x1 - k.x, dy = y1 - k.y, dz = z1 - k.z;
            float d = fmaf(dx, dx, fmaf(dy, dy, dz * dz));
            float s = __fdividef(kFACT, fmaxf(d, kEPS));
            float w = __expf(s - smax);
            Z += w;
            a0 = fmaf(w, k.x, a0);
            a1 = fmaf(w, k.y, a1);
            a2 = fmaf(w, k.z, a2);
            a3 = fmaf(w, k.w, a3);
        }
        #pragma unroll
        for (int o = 16; o; o >>= 1) {
            Z  += __shfl_xor_sync(0xffffffffu, Z,  o);
            a0 += __shfl_xor_sync(0xffffffffu, a0, o);
            a1 += __shfl_xor_sync(0xffffffffu, a1, o);
            a2 += __shfl_xor_sync(0xffffffffu, a2, o);
            a3 += __shfl_xor_sync(0xffffffffu, a3, o);
        }

        if (lane == 0) {
            float rz = 1.0f / Z;
            float q0 = a0 * rz, q1 = a1 * rz, q2 = a2 * rz, q3 = a3 * rz;
            float dx = x1 - q0, dy = y1 - q1, dz = z1 - q2, dw = w1 - q3;
            g_pcn[b][0][n] = q0;
            g_pcn[b][1][n] = q1;
            g_pcn[b][2][n] = q2;
            g_dist[b][n] = sqrtf(dx * dx + dy * dy + dz * dz + dw * dw);
        }
    }
}

// ---------------------------------------------------------------------------
// Kernel 2: per-batch finalize (mean, indexor, centroids, H, SVD, R, t, T, q)
// ---------------------------------------------------------------------------
__device__ __forceinline__ double blockSum(double v) {
    __shared__ double tmp[8];
    const int lane = threadIdx.x & 31;
    const int w = threadIdx.x >> 5;
    #pragma unroll
    for (int o = 16; o; o >>= 1) v += __shfl_xor_sync(0xffffffffu, v, o);
    __syncthreads();
    if (lane == 0) tmp[w] = v;
    __syncthreads();
    double r = 0.0;
    #pragma unroll
    for (int i = 0; i < 8; ++i) r += tmp[i];
    return r;
}

__global__ void __launch_bounds__(256)
cpnet_finalize(const float* __restrict__ pc1, float* __restrict__ out) {
    const int b = blockIdx.x;
    const float* p1 = pc1 + (size_t)b * 4 * NN;
    const int tid = threadIdx.x;

    // mean dist
    double s = 0.0;
    for (int n = tid; n < NN; n += 256) s += (double)g_dist[b][n];
    s = blockSum(s);
    const float mean = (float)(s * (1.0 / (double)NN));

    // indexor + centroid sums
    double sw = 0, s1x = 0, s1y = 0, s1z = 0, s2x = 0, s2y = 0, s2z = 0;
    for (int n = tid; n < NN; n += 256) {
        float dist = g_dist[b][n];
        float z = (dist - mean - kEPS) * 1e10f;
        float ind = 1.0f / (1.0f + __expf(z));
        sw  += (double)ind;
        s1x += (double)(ind * p1[n]);
        s1y += (double)(ind * p1[NN + n]);
        s1z += (double)(ind * p1[2 * NN + n]);
        s2x += (double)(ind * g_pcn[b][0][n]);
        s2y += (double)(ind * g_pcn[b][1][n]);
        s2z += (double)(ind * g_pcn[b][2][n]);
    }
    sw  = blockSum(sw);
    s1x = blockSum(s1x); s1y = blockSum(s1y); s1z = blockSum(s1z);
    s2x = blockSum(s2x); s2y = blockSum(s2y); s2z = blockSum(s2z);
    const float c1x = (float)(s1x / sw), c1y = (float)(s1y / sw), c1z = (float)(s1z / sw);
    const float c2x = (float)(s2x / sw), c2y = (float)(s2y / sw), c2z = (float)(s2z / sw);

    // H = p1c^T @ p2c  (indexor applied to both sides, matching reference)
    double h[9];
    #pragma unroll
    for (int i = 0; i < 9; ++i) h[i] = 0.0;
    for (int n = tid; n < NN; n += 256) {
        float dist = g_dist[b][n];
        float z = (dist - mean - kEPS) * 1e10f;
        float ind = 1.0f / (1.0f + __expf(z));
        float ax = (p1[n] - c1x) * ind;
        float ay = (p1[NN + n] - c1y) * ind;
        float az = (p1[2 * NN + n] - c1z) * ind;
        float bx = (g_pcn[b][0][n] - c2x) * ind;
        float by = (g_pcn[b][1][n] - c2y) * ind;
        float bz = (g_pcn[b][2][n] - c2z) * ind;
        h[0] += (double)(ax * bx); h[1] += (double)(ax * by); h[2] += (double)(ax * bz);
        h[3] += (double)(ay * bx); h[4] += (double)(ay * by); h[5] += (double)(ay * bz);
        h[6] += (double)(az * bx); h[7] += (double)(az * by); h[8] += (double)(az * bz);
    }
    #pragma unroll
    for (int i = 0; i < 9; ++i) h[i] = blockSum(h[i]);

    if (tid == 0) {
        double H[3][3] = {{h[0], h[1], h[2]}, {h[3], h[4], h[5]}, {h[6], h[7], h[8]}};
        // S = H^T H (symmetric PSD), Jacobi eigendecomposition -> V, eigvals
        double S[3][3];
        for (int i = 0; i < 3; ++i)
            for (int j = 0; j < 3; ++j)
                S[i][j] = H[0][i] * H[0][j] + H[1][i] * H[1][j] + H[2][i] * H[2][j];
        double V[3][3] = {{1, 0, 0}, {0, 1, 0}, {0, 0, 1}};
        const int PP[3] = {0, 0, 1}, QQ[3] = {1, 2, 2};
        for (int it = 0; it < 24; ++it) {
            int p = PP[it % 3], q = QQ[it % 3];
            double apq = S[p][q];
            if (fabs(apq) < 1e-300) continue;
            double theta = (S[q][q] - S[p][p]) / (2.0 * apq);
            double t = copysign(1.0, theta) / (fabs(theta) + sqrt(theta * theta + 1.0));
            double c = 1.0 / sqrt(t * t + 1.0);
            double sn = t * c;
            for (int k = 0; k < 3; ++k) {
                double skp = S[k][p], skq = S[k][q];
                S[k][p] = c * skp - sn * skq;
                S[k][q] = sn * skp + c * skq;
            }
            for (int k = 0; k < 3; ++k) {
                double spk = S[p][k], sqk = S[q][k];
                S[p][k] = c * spk - sn * sqk;
                S[q][k] = sn * spk + c * sqk;
            }
            for (int k = 0; k < 3; ++k) {
                double vkp = V[k][p], vkq = V[k][q];
                V[k][p] = c * vkp - sn * vkq;
                V[k][q] = sn * vkp + c * vkq;
            }
        }
        double ev[3] = {S[0][0], S[1][1], S[2][2]};
        for (int a = 0; a < 2; ++a)
            for (int bc = a + 1; bc < 3; ++bc)
                if (ev[bc] > ev[a]) {
                    double te = ev[a]; ev[a] = ev[bc]; ev[bc] = te;
                    for (int k = 0; k < 3; ++k) {
                        double tv = V[k][a]; V[k][a] = V[k][bc]; V[k][bc] = tv;
                    }
                }
        // U = H V S^{-1} (honest SVD so det(U)*det(V) matches reference)
        double U[3][3];
        for (int j = 0; j < 3; ++j) {
            double sig = sqrt(fmax(ev[j], 0.0));
            double inv = (sig > 1e-20) ? (1.0 / sig) : 0.0;
            for (int i = 0; i < 3; ++i)
                U[i][j] = (H[i][0] * V[0][j] + H[i][1] * V[1][j] + H[i][2] * V[2][j]) * inv;
        }
        auto det3 = [](double M[3][3]) {
            return M[0][0] * (M[1][1] * M[2][2] - M[1][2] * M[2][1])
                 - M[0][1] * (M[1][0] * M[2][2] - M[1][2] * M[2][0])
                 + M[0][2] * (M[1][0] * M[2][1] - M[1][1] * M[2][0]);
        };
        double sign = (det3(U) * det3(V) < 0.0) ? -1.0 : 1.0;
        V[0][2] *= sign; V[1][2] *= sign; V[2][2] *= sign;
        double R[3][3];
        for (int i = 0; i < 3; ++i)
            for (int j = 0; j < 3; ++j)
                R[i][j] = V[i][0] * U[j][0] + V[i][1] * U[j][1] + V[i][2] * U[j][2];
        double c1v[3] = {c1x, c1y, c1z}, c2v[3] = {c2x, c2y, c2z};
        double tt[3];
        for (int i = 0; i < 3; ++i)
            tt[i] = c2v[i] - (R[i][0] * c1v[0] + R[i][1] * c1v[1] + R[i][2] * c1v[2]);

        // Outputs: T [B,4,4], then q [B,4], then t [B,3] (flat concat, float32)
        float* T = out + b * 16;
        for (int i = 0; i < 3; ++i) {
            T[i * 4 + 0] = (float)R[i][0];
            T[i * 4 + 1] = (float)R[i][1];
            T[i * 4 + 2] = (float)R[i][2];
            T[i * 4 + 3] = (float)tt[i];
        }
        T[12] = 0.f; T[13] = 0.f; T[14] = 0.f; T[15] = 1.f;

        auto sgn = [](double x) { return x >= 0.0 ? 1.0 : -1.0; };
        double qw = 0.5 * sqrt(fmax(1.0 + R[0][0] + R[1][1] + R[2][2], 1e-12));
        double qx = 0.5 * sqrt(fmax(1.0 + R[0][0] - R[1][1] - R[2][2], 1e-12)) * sgn(R[2][1] - R[1][2]);
        double qy = 0.5 * sqrt(fmax(1.0 - R[0][0] + R[1][1] - R[2][2], 1e-12)) * sgn(R[0][2] - R[2][0]);
        double qz = 0.5 * sqrt(fmax(1.0 - R[0][0] - R[1][1] + R[2][2], 1e-12)) * sgn(R[1][0] - R[0][1]);
        float* qo = out + BB * 16 + b * 4;
        qo[0] = (float)qw; qo[1] = (float)qx; qo[2] = (float)qy; qo[3] = (float)qz;
        float* to = out + BB * 16 + BB * 4 + b * 3;
        to[0] = (float)tt[0]; to[1] = (float)tt[1]; to[2] = (float)tt[2];
    }
}

// ---------------------------------------------------------------------------
extern "C" void kernel_launch(void* const* d_in, const int* in_sizes, int n_in,
                              void* d_out, int out_size) {
    const float* pc1 = (const float*)d_in[0];
    const float* pc2 = (const float*)d_in[1];
    float* out = (float*)d_out;

    cudaFuncSetAttribute(cpnet_rows, cudaFuncAttributeMaxDynamicSharedMemorySize,
                         NN * (int)sizeof(float4));

    dim3 grid(NN / 32, BB);  // 128 x 8 = 1024 CTAs, 32 rows each
    cpnet_rows<<<grid, 256, NN * sizeof(float4)>>>(pc1, pc2);
    cpnet_finalize<<<BB, 256>>>(pc1, out);
}

// round 2
// speedup vs baseline: 1.7954x; 1.7954x over previous
#include <cuda_runtime.h>
#include <math.h>
#include <float.h>

#define BB 8
#define NN 4096

static __device__ __constant__ float kEPS  = 1e-5f;
static __device__ __constant__ float kF2   = 2.8853900817779268f; // FACT * log2(e)

// Scratch (device globals; no allocation allowed)
__device__ float g_pcn[BB][3][NN];
__device__ float g_dist[BB][NN];

__device__ __forceinline__ float frcp(float x) {
    float r; asm("rcp.approx.f32 %0, %1;" : "=f"(r) : "f"(x)); return r;
}
__device__ __forceinline__ float fex2(float x) {
    float r; asm("ex2.approx.f32 %0, %1;" : "=f"(r) : "f"(x)); return r;
}

// ---------------------------------------------------------------------------
// Kernel 1: per (b, n) row — min-d pass, softmax pass, pc_nearest, dist.
// Each warp handles 2 rows per SMEM element load (halves LDS traffic).
// SMEM tile: float4 = (x, y, z, |p|^2) per pc2 point.
// ---------------------------------------------------------------------------
__global__ void __launch_bounds__(256, 3)
cpnet_rows(const float* __restrict__ pc1, const float* __restrict__ pc2) {
    extern __shared__ float4 sk[];  // 4096 x float4 = 64KB
    const int b = blockIdx.y;
    const float* p2 = pc2 + (size_t)b * 4 * NN;
    const float* p1 = pc1 + (size_t)b * 4 * NN;

    for (int i = threadIdx.x; i < NN; i += blockDim.x) {
        float x = p2[i], y = p2[NN + i], z = p2[2 * NN + i];
        sk[i] = make_float4(x, y, z, fmaf(z, z, fmaf(y, y, x * x)));
    }
    __syncthreads();

    const int warp = threadIdx.x >> 5;
    const int lane = threadIdx.x & 31;

    // Two rows per warp: n0, n0+1. 16 rows per CTA.
    const int n0 = (blockIdx.x << 4) + (warp << 1);

    const float xA = p1[n0],     yA = p1[NN + n0],     zA = p1[2 * NN + n0];
    const float xB = p1[n0 + 1], yB = p1[NN + n0 + 1], zB = p1[2 * NN + n0 + 1];
    const float rA = fmaf(zA, zA, fmaf(yA, yA, xA * xA));
    const float rB = fmaf(zB, zB, fmaf(yB, yB, xB * xB));
    const float nxA = -2.f * xA, nyA = -2.f * yA, nzA = -2.f * zA;
    const float nxB = -2.f * xB, nyB = -2.f * yB, nzB = -2.f * zB;

    // ---- Pass 1: min squared distance for both rows ----
    float dmA = FLT_MAX, dmB = FLT_MAX;
    #pragma unroll 4
    for (int m = lane; m < NN; m += 32) {
        float4 k = sk[m];
        float dA = fmaf(nxA, k.x, fmaf(nyA, k.y, fmaf(nzA, k.z, rA + k.w)));
        float dB = fmaf(nxB, k.x, fmaf(nyB, k.y, fmaf(nzB, k.z, rB + k.w)));
        dmA = fminf(dmA, dA);
        dmB = fminf(dmB, dB);
    }
    #pragma unroll
    for (int o = 16; o; o >>= 1) {
        dmA = fminf(dmA, __shfl_xor_sync(0xffffffffu, dmA, o));
        dmB = fminf(dmB, __shfl_xor_sync(0xffffffffu, dmB, o));
    }
    // softmax max in log2 domain: c = F2 / max(dmin, EPS)
    const float cA = kF2 * frcp(fmaxf(dmA, kEPS));
    const float cB = kF2 * frcp(fmaxf(dmB, kEPS));

    // ---- Pass 2: exp2 weights + weighted accumulation ----
    float ZA = 0.f, a0A = 0.f, a1A = 0.f, a2A = 0.f;
    float ZB = 0.f, a0B = 0.f, a1B = 0.f, a2B = 0.f;
    #pragma unroll 4
    for (int m = lane; m < NN; m += 32) {
        float4 k = sk[m];
        float dA = fmaf(nxA, k.x, fmaf(nyA, k.y, fmaf(nzA, k.z, rA + k.w)));
        float dB = fmaf(nxB, k.x, fmaf(nyB, k.y, fmaf(nzB, k.z, rB + k.w)));
        dA = fmaxf(dA, kEPS);
        dB = fmaxf(dB, kEPS);
        float wA = fex2(fmaf(frcp(dA), kF2, -cA));
        float wB = fex2(fmaf(frcp(dB), kF2, -cB));
        ZA += wA;
        a0A = fmaf(wA, k.x, a0A);
        a1A = fmaf(wA, k.y, a1A);
        a2A = fmaf(wA, k.z, a2A);
        ZB += wB;
        a0B = fmaf(wB, k.x, a0B);
        a1B = fmaf(wB, k.y, a1B);
        a2B = fmaf(wB, k.z, a2B);
    }
    #pragma unroll
    for (int o = 16; o; o >>= 1) {
        ZA  += __shfl_xor_sync(0xffffffffu, ZA,  o);
        a0A += __shfl_xor_sync(0xffffffffu, a0A, o);
        a1A += __shfl_xor_sync(0xffffffffu, a1A, o);
        a2A += __shfl_xor_sync(0xffffffffu, a2A, o);
        ZB  += __shfl_xor_sync(0xffffffffu, ZB,  o);
        a0B += __shfl_xor_sync(0xffffffffu, a0B, o);
        a1B += __shfl_xor_sync(0xffffffffu, a1B, o);
        a2B += __shfl_xor_sync(0xffffffffu, a2B, o);
    }

    if (lane == 0) {
        {
            float rz = 1.0f / ZA;
            float q0 = a0A * rz, q1 = a1A * rz, q2 = a2A * rz;
            float dx = xA - q0, dy = yA - q1, dz = zA - q2;
            g_pcn[b][0][n0] = q0; g_pcn[b][1][n0] = q1; g_pcn[b][2][n0] = q2;
            g_dist[b][n0] = sqrtf(dx * dx + dy * dy + dz * dz);
        }
        {
            float rz = 1.0f / ZB;
            float q0 = a0B * rz, q1 = a1B * rz, q2 = a2B * rz;
            float dx = xB - q0, dy = yB - q1, dz = zB - q2;
            g_pcn[b][0][n0 + 1] = q0; g_pcn[b][1][n0 + 1] = q1; g_pcn[b][2][n0 + 1] = q2;
            g_dist[b][n0 + 1] = sqrtf(dx * dx + dy * dy + dz * dz);
        }
    }
}

// ---------------------------------------------------------------------------
// Kernel 2: per-batch finalize. Double only for the parallel reductions;
// serial tail (SVD / R / t / quat) in fp32 with MUFU.
// ---------------------------------------------------------------------------
__device__ __forceinline__ double blockSumD(double v) {
    __shared__ double tmp[8];
    const int lane = threadIdx.x & 31;
    const int w = threadIdx.x >> 5;
    #pragma unroll
    for (int o = 16; o; o >>= 1) v += __shfl_xor_sync(0xffffffffu, v, o);
    __syncthreads();
    if (lane == 0) tmp[w] = v;
    __syncthreads();
    double r = 0.0;
    #pragma unroll
    for (int i = 0; i < 8; ++i) r += tmp[i];
    return r;
}

__global__ void __launch_bounds__(256)
cpnet_finalize(const float* __restrict__ pc1, float* __restrict__ out) {
    const int b = blockIdx.x;
    const float* p1 = pc1 + (size_t)b * 4 * NN;
    const int tid = threadIdx.x;

    // mean dist (double reduce — cheap, parallel)
    double sd = 0.0;
    for (int n = tid; n < NN; n += 256) sd += (double)g_dist[b][n];
    sd = blockSumD(sd);
    const float mean = (float)(sd * (1.0 / (double)NN));

    // single pass: 16 uncentered moments (float partials, double combine)
    // P: [sw, s1x, s1y, s1z, s2x, s2y, s2z, M00..M22]
    float P[16];
    #pragma unroll
    for (int i = 0; i < 16; ++i) P[i] = 0.f;
    for (int n = tid; n < NN; n += 256) {
        float dist = g_dist[b][n];
        float z = (dist - mean - kEPS) * 1e10f;
        float ind = 1.0f / (1.0f + __expf(z));
        float ax = p1[n], ay = p1[NN + n], az = p1[2 * NN + n];
        float bx = g_pcn[b][0][n], by = g_pcn[b][1][n], bz = g_pcn[b][2][n];
        float iax = ind * ax, iay = ind * ay, iaz = ind * az;
        P[0] += ind;
        P[1] += iax; P[2] += iay; P[3] += iaz;
        P[4] += ind * bx; P[5] += ind * by; P[6] += ind * bz;
        P[7]  += iax * bx; P[8]  += iax * by; P[9]  += iax * bz;
        P[10] += iay * bx; P[11] += iay * by; P[12] += iay * bz;
        P[13] += iaz * bx; P[14] += iaz * by; P[15] += iaz * bz;
    }
    double S[16];
    #pragma unroll
    for (int i = 0; i < 16; ++i) S[i] = blockSumD((double)P[i]);

    if (tid == 0) {
        const double sw = S[0];
        const double inv_sw = 1.0 / sw;
        double c1d[3] = {S[1] * inv_sw, S[2] * inv_sw, S[3] * inv_sw};
        double c2d[3] = {S[4] * inv_sw, S[5] * inv_sw, S[6] * inv_sw};
        // H = M - s1 s2^T / sw  (valid: indexor saturates to {0,1})
        float H[3][3];
        #pragma unroll
        for (int i = 0; i < 3; ++i)
            #pragma unroll
            for (int j = 0; j < 3; ++j)
                H[i][j] = (float)(S[7 + i * 3 + j] - S[1 + i] * S[4 + j] * inv_sw);

        // G = H^T H, fp32 Jacobi eigendecomposition -> V, ev
        float G[3][3];
        #pragma unroll
        for (int i = 0; i < 3; ++i)
            #pragma unroll
            for (int j = 0; j < 3; ++j)
                G[i][j] = H[0][i] * H[0][j] + H[1][i] * H[1][j] + H[2][i] * H[2][j];
        float V[3][3] = {{1, 0, 0}, {0, 1, 0}, {0, 0, 1}};
        const int PP[3] = {0, 0, 1}, QQ[3] = {1, 2, 2};
        #pragma unroll
        for (int it = 0; it < 18; ++it) {
            int p = PP[it % 3], q = QQ[it % 3];
            float apq = G[p][q];
            if (fabsf(apq) > 1e-25f) {
                float theta = (G[q][q] - G[p][p]) / (2.0f * apq);
                float t = copysignf(1.0f, theta) / (fabsf(theta) + sqrtf(theta * theta + 1.0f));
                float c = rsqrtf(t * t + 1.0f);
                float sn = t * c;
                #pragma unroll
                for (int k = 0; k < 3; ++k) {
                    float gkp = G[k][p], gkq = G[k][q];
                    G[k][p] = c * gkp - sn * gkq;
                    G[k][q] = sn * gkp + c * gkq;
                }
                #pragma unroll
                for (int k = 0; k < 3; ++k) {
                    float gpk = G[p][k], gqk = G[q][k];
                    G[p][k] = c * gpk - sn * gqk;
                    G[q][k] = sn * gpk + c * gqk;
                }
                #pragma unroll
                for (int k = 0; k < 3; ++k) {
                    float vkp = V[k][p], vkq = V[k][q];
                    V[k][p] = c * vkp - sn * vkq;
                    V[k][q] = sn * vkp + c * vkq;
                }
            }
        }
        float ev[3] = {G[0][0], G[1][1], G[2][2]};
        #pragma unroll
        for (int a = 0; a < 2; ++a)
            #pragma unroll
            for (int bc = 1; bc < 3; ++bc)
                if (bc > a && ev[bc] > ev[a]) {
                    float te = ev[a]; ev[a] = ev[bc]; ev[bc] = te;
                    #pragma unroll
                    for (int k = 0; k < 3; ++k) {
                        float tv = V[k][a]; V[k][a] = V[k][bc]; V[k][bc] = tv;
                    }
                }
        // U = H V / sigma
        float U[3][3];
        #pragma unroll
        for (int j = 0; j < 3; ++j) {
            float sig = sqrtf(fmaxf(ev[j], 0.f));
            float inv = (sig > 1e-20f) ? (1.0f / sig) : 0.f;
            #pragma unroll
            for (int i = 0; i < 3; ++i)
                U[i][j] = (H[i][0] * V[0][j] + H[i][1] * V[1][j] + H[i][2] * V[2][j]) * inv;
        }
        auto det3 = [](float M[3][3]) {
            return M[0][0] * (M[1][1] * M[2][2] - M[1][2] * M[2][1])
                 - M[0][1] * (M[1][0] * M[2][2] - M[1][2] * M[2][0])
                 + M[0][2] * (M[1][0] * M[2][1] - M[1][1] * M[2][0]);
        };
        float sign = (det3(U) * det3(V) < 0.f) ? -1.f : 1.f;
        V[0][2] *= sign; V[1][2] *= sign; V[2][2] *= sign;
        float R[3][3];
        #pragma unroll
        for (int i = 0; i < 3; ++i)
            #pragma unroll
            for (int j = 0; j < 3; ++j)
                R[i][j] = V[i][0] * U[j][0] + V[i][1] * U[j][1] + V[i][2] * U[j][2];
        float c1v[3] = {(float)c1d[0], (float)c1d[1], (float)c1d[2]};
        float c2v[3] = {(float)c2d[0], (float)c2d[1], (float)c2d[2]};
        float tt[3];
        #pragma unroll
        for (int i = 0; i < 3; ++i)
            tt[i] = c2v[i] - (R[i][0] * c1v[0] + R[i][1] * c1v[1] + R[i][2] * c1v[2]);

        // Outputs: T [B,4,4], q [B,4], t [B,3] flat concat (float32)
        float* T = out + b * 16;
        #pragma unroll
        for (int i = 0; i < 3; ++i) {
            T[i * 4 + 0] = R[i][0];
            T[i * 4 + 1] = R[i][1];
            T[i * 4 + 2] = R[i][2];
            T[i * 4 + 3] = tt[i];
        }
        T[12] = 0.f; T[13] = 0.f; T[14] = 0.f; T[15] = 1.f;

        auto sgn = [](float x) { return x >= 0.f ? 1.f : -1.f; };
        float qw = 0.5f * sqrtf(fmaxf(1.f + R[0][0] + R[1][1] + R[2][2], 1e-12f));
        float qx = 0.5f * sqrtf(fmaxf(1.f + R[0][0] - R[1][1] - R[2][2], 1e-12f)) * sgn(R[2][1] - R[1][2]);
        float qy = 0.5f * sqrtf(fmaxf(1.f - R[0][0] + R[1][1] - R[2][2], 1e-12f)) * sgn(R[0][2] - R[2][0]);
        float qz = 0.5f * sqrtf(fmaxf(1.f - R[0][0] - R[1][1] + R[2][2], 1e-12f)) * sgn(R[1][0] - R[0][1]);
        float* qo = out + BB * 16 + b * 4;
        qo[0] = qw; qo[1] = qx; qo[2] = qy; qo[3] = qz;
        float* to = out + BB * 16 + BB * 4 + b * 3;
        to[0] = tt[0]; to[1] = tt[1]; to[2] = tt[2];
    }
}

// ---------------------------------------------------------------------------
extern "C" void kernel_launch(void* const* d_in, const int* in_sizes, int n_in,
                              void* d_out, int out_size) {
    const float* pc1 = (const float*)d_in[0];
    const float* pc2 = (const float*)d_in[1];
    float* out = (float*)d_out;

    cudaFuncSetAttribute(cpnet_rows, cudaFuncAttributeMaxDynamicSharedMemorySize,
                         NN * (int)sizeof(float4));

    dim3 grid(NN / 16, BB);  // 256 x 8 = 2048 CTAs, 16 rows each (2 per warp)
    cpnet_rows<<<grid, 256, NN * sizeof(float4)>>>(pc1, pc2);
    cpnet_finalize<<<BB, 256>>>(pc1, out);
}

// round 3
// speedup vs baseline: 1.9923x; 1.1097x over previous
#include <cuda_runtime.h>
#include <math.h>
#include <float.h>

#define BB 8
#define NN 4096
#define NP (NN / 2)  // element pairs

static __device__ __constant__ float kEPS = 1e-5f;
static __device__ __constant__ float kF2  = 2.8853900817779268f; // FACT * log2(e)

// Scratch (device globals; no allocation allowed)
__device__ float g_pcn[BB][3][NN];
__device__ float g_dist[BB][NN];

typedef unsigned long long u64;

__device__ __forceinline__ float frcp(float x) {
    float r; asm("rcp.approx.f32 %0, %1;" : "=f"(r) : "f"(x)); return r;
}
__device__ __forceinline__ float fex2(float x) {
    float r; asm("ex2.approx.f32 %0, %1;" : "=f"(r) : "f"(x)); return r;
}
__device__ __forceinline__ u64 pk2(float lo, float hi) {
    u64 r; asm("mov.b64 %0, {%1, %2};" : "=l"(r) : "f"(lo), "f"(hi)); return r;
}
__device__ __forceinline__ void upk2(u64 v, float& lo, float& hi) {
    asm("mov.b64 {%0, %1}, %2;" : "=f"(lo), "=f"(hi) : "l"(v));
}
__device__ __forceinline__ u64 fma2(u64 a, u64 b, u64 c) {
    u64 d; asm("fma.rn.f32x2 %0, %1, %2, %3;" : "=l"(d) : "l"(a), "l"(b), "l"(c)); return d;
}
__device__ __forceinline__ u64 add2(u64 a, u64 b) {
    u64 d; asm("add.rn.f32x2 %0, %1, %2;" : "=l"(d) : "l"(a), "l"(b)); return d;
}

// ---------------------------------------------------------------------------
// Kernel 1: per (b, n) row — min-d pass, softmax pass, pc_nearest, dist.
// 2 rows per warp; pc2 tiled in SMEM as element pairs for f32x2 math.
//   sXY[p] = (x[2p], x[2p+1], y[2p], y[2p+1])
//   sZR[p] = (z[2p], z[2p+1], r[2p], r[2p+1]),  r = |p2|^2 (xyz)
// ---------------------------------------------------------------------------
__global__ void __launch_bounds__(256)
cpnet_rows(const float* __restrict__ pc1, const float* __restrict__ pc2) {
    extern __shared__ float4 smem[];
    float4* sXY = smem;        // 2048 float4 = 32KB
    float4* sZR = smem + NP;   // 2048 float4 = 32KB
    const int b = blockIdx.y;
    const float* p2 = pc2 + (size_t)b * 4 * NN;
    const float* p1 = pc1 + (size_t)b * 4 * NN;

    {
        const float2* px = (const float2*)p2;
        const float2* py = (const float2*)(p2 + NN);
        const float2* pz = (const float2*)(p2 + 2 * NN);
        for (int i = threadIdx.x; i < NP; i += blockDim.x) {
            float2 x = px[i], y = py[i], z = pz[i];
            sXY[i] = make_float4(x.x, x.y, y.x, y.y);
            float r0 = fmaf(z.x, z.x, fmaf(y.x, y.x, x.x * x.x));
            float r1 = fmaf(z.y, z.y, fmaf(y.y, y.y, x.y * x.y));
            sZR[i] = make_float4(z.x, z.y, r0, r1);
        }
    }
    __syncthreads();

    const int warp = threadIdx.x >> 5;
    const int lane = threadIdx.x & 31;
    const int n0 = (blockIdx.x << 4) + (warp << 1);  // 16 rows/CTA, 2 rows/warp

    const float xA = p1[n0],     yA = p1[NN + n0],     zA = p1[2 * NN + n0];
    const float xB = p1[n0 + 1], yB = p1[NN + n0 + 1], zB = p1[2 * NN + n0 + 1];
    const float rA = fmaf(zA, zA, fmaf(yA, yA, xA * xA));
    const float rB = fmaf(zB, zB, fmaf(yB, yB, xB * xB));

    const u64 nxA2 = pk2(-2.f * xA, -2.f * xA), nyA2 = pk2(-2.f * yA, -2.f * yA);
    const u64 nzA2 = pk2(-2.f * zA, -2.f * zA), rA2  = pk2(rA, rA);
    const u64 nxB2 = pk2(-2.f * xB, -2.f * xB), nyB2 = pk2(-2.f * yB, -2.f * yB);
    const u64 nzB2 = pk2(-2.f * zB, -2.f * zB), rB2  = pk2(rB, rB);

    // ---- Pass 1: min squared distance (packed fma, scalar min) ----
    float dmA0 = FLT_MAX, dmA1 = FLT_MAX, dmB0 = FLT_MAX, dmB1 = FLT_MAX;
    #pragma unroll 4
    for (int p = lane; p < NP; p += 32) {
        float4 kxy = sXY[p];
        float4 kzr = sZR[p];
        u64 x01 = pk2(kxy.x, kxy.y), y01 = pk2(kxy.z, kxy.w);
        u64 z01 = pk2(kzr.x, kzr.y), r01 = pk2(kzr.z, kzr.w);
        u64 dA = fma2(nzA2, z01, fma2(nyA2, y01, fma2(nxA2, x01, add2(r01, rA2))));
        u64 dB = fma2(nzB2, z01, fma2(nyB2, y01, fma2(nxB2, x01, add2(r01, rB2))));
        float a0, a1, b0, b1;
        upk2(dA, a0, a1); upk2(dB, b0, b1);
        dmA0 = fminf(dmA0, a0); dmA1 = fminf(dmA1, a1);
        dmB0 = fminf(dmB0, b0); dmB1 = fminf(dmB1, b1);
    }
    float dmA = fminf(dmA0, dmA1), dmB = fminf(dmB0, dmB1);
    #pragma unroll
    for (int o = 16; o; o >>= 1) {
        dmA = fminf(dmA, __shfl_xor_sync(0xffffffffu, dmA, o));
        dmB = fminf(dmB, __shfl_xor_sync(0xffffffffu, dmB, o));
    }
    const float cA = kF2 * frcp(fmaxf(dmA, kEPS));
    const float cB = kF2 * frcp(fmaxf(dmB, kEPS));
    const u64 ncA2 = pk2(-cA, -cA), ncB2 = pk2(-cB, -cB);
    const u64 F2p  = pk2(kF2, kF2);

    // ---- Pass 2: exp2 weights + packed accumulation ----
    u64 zAcc = 0, a0A = 0, a1A = 0, a2A = 0;  // 0ull == packed (0.f, 0.f)
    u64 zBcc = 0, a0B = 0, a1B = 0, a2B = 0;
    #pragma unroll 4
    for (int p = lane; p < NP; p += 32) {
        float4 kxy = sXY[p];
        float4 kzr = sZR[p];
        u64 x01 = pk2(kxy.x, kxy.y), y01 = pk2(kxy.z, kxy.w);
        u64 z01 = pk2(kzr.x, kzr.y), r01 = pk2(kzr.z, kzr.w);

        u64 dA = fma2(nzA2, z01, fma2(nyA2, y01, fma2(nxA2, x01, add2(r01, rA2))));
        u64 dB = fma2(nzB2, z01, fma2(nyB2, y01, fma2(nxB2, x01, add2(r01, rB2))));

        float da0, da1, db0, db1;
        upk2(dA, da0, da1); upk2(dB, db0, db1);
        float iA0 = frcp(fmaxf(da0, kEPS)), iA1 = frcp(fmaxf(da1, kEPS));
        float iB0 = frcp(fmaxf(db0, kEPS)), iB1 = frcp(fmaxf(db1, kEPS));

        u64 argA = fma2(pk2(iA0, iA1), F2p, ncA2);
        u64 argB = fma2(pk2(iB0, iB1), F2p, ncB2);
        float gA0, gA1, gB0, gB1;
        upk2(argA, gA0, gA1); upk2(argB, gB0, gB1);
        u64 wA = pk2(fex2(gA0), fex2(gA1));
        u64 wB = pk2(fex2(gB0), fex2(gB1));

        zAcc = add2(zAcc, wA);
        a0A = fma2(wA, x01, a0A);
        a1A = fma2(wA, y01, a1A);
        a2A = fma2(wA, z01, a2A);
        zBcc = add2(zBcc, wB);
        a0B = fma2(wB, x01, a0B);
        a1B = fma2(wB, y01, a1B);
        a2B = fma2(wB, z01, a2B);
    }

    float ZA, t1, v0A, v1A, v2A, ZB, v0B, v1B, v2B, t2;
    { float lo, hi;
      upk2(zAcc, lo, hi); ZA  = lo + hi;
      upk2(a0A, lo, hi);  v0A = lo + hi;
      upk2(a1A, lo, hi);  v1A = lo + hi;
      upk2(a2A, lo, hi);  v2A = lo + hi;
      upk2(zBcc, lo, hi); ZB  = lo + hi;
      upk2(a0B, lo, hi);  v0B = lo + hi;
      upk2(a1B, lo, hi);  v1B = lo + hi;
      upk2(a2B, lo, hi);  v2B = lo + hi;
      (void)t1; (void)t2; }
    #pragma unroll
    for (int o = 16; o; o >>= 1) {
        ZA  += __shfl_xor_sync(0xffffffffu, ZA,  o);
        v0A += __shfl_xor_sync(0xffffffffu, v0A, o);
        v1A += __shfl_xor_sync(0xffffffffu, v1A, o);
        v2A += __shfl_xor_sync(0xffffffffu, v2A, o);
        ZB  += __shfl_xor_sync(0xffffffffu, ZB,  o);
        v0B += __shfl_xor_sync(0xffffffffu, v0B, o);
        v1B += __shfl_xor_sync(0xffffffffu, v1B, o);
        v2B += __shfl_xor_sync(0xffffffffu, v2B, o);
    }

    if (lane == 0) {
        {
            float rz = 1.0f / ZA;
            float q0 = v0A * rz, q1 = v1A * rz, q2 = v2A * rz;
            float dx = xA - q0, dy = yA - q1, dz = zA - q2;
            g_pcn[b][0][n0] = q0; g_pcn[b][1][n0] = q1; g_pcn[b][2][n0] = q2;
            g_dist[b][n0] = sqrtf(dx * dx + dy * dy + dz * dz);
        }
        {
            float rz = 1.0f / ZB;
            float q0 = v0B * rz, q1 = v1B * rz, q2 = v2B * rz;
            float dx = xB - q0, dy = yB - q1, dz = zB - q2;
            g_pcn[b][0][n0 + 1] = q0; g_pcn[b][1][n0 + 1] = q1; g_pcn[b][2][n0 + 1] = q2;
            g_dist[b][n0 + 1] = sqrtf(dx * dx + dy * dy + dz * dz);
        }
    }
}

// ---------------------------------------------------------------------------
// Kernel 2: per-batch finalize. Batched reductions (2 sync points), 512 thr.
// ---------------------------------------------------------------------------
#define FTH 512

__global__ void __launch_bounds__(FTH)
cpnet_finalize(const float* __restrict__ pc1, float* __restrict__ out) {
    const int b = blockIdx.x;
    const float* p1 = pc1 + (size_t)b * 4 * NN;
    const int tid = threadIdx.x;
    const int lane = tid & 31;
    const int w = tid >> 5;  // 16 warps

    __shared__ double smD[16][17];
    __shared__ double smMean[16];

    // ---- mean dist ----
    double sd = 0.0;
    for (int n = tid; n < NN; n += FTH) sd += (double)g_dist[b][n];
    #pragma unroll
    for (int o = 16; o; o >>= 1) sd += __shfl_xor_sync(0xffffffffu, sd, o);
    if (lane == 0) smMean[w] = sd;
    __syncthreads();
    double ms = 0.0;
    #pragma unroll
    for (int i = 0; i < 16; ++i) ms += smMean[i];
    const float mean = (float)(ms * (1.0 / (double)NN));

    // ---- single pass: 16 uncentered moments ----
    float P[16];
    #pragma unroll
    for (int i = 0; i < 16; ++i) P[i] = 0.f;
    for (int n = tid; n < NN; n += FTH) {
        float dist = g_dist[b][n];
        float z = (dist - mean - kEPS) * 1e10f;
        float ind = 1.0f / (1.0f + __expf(z));
        float ax = p1[n], ay = p1[NN + n], az = p1[2 * NN + n];
        float bx = g_pcn[b][0][n], by = g_pcn[b][1][n], bz = g_pcn[b][2][n];
        float iax = ind * ax, iay = ind * ay, iaz = ind * az;
        P[0] += ind;
        P[1] += iax; P[2] += iay; P[3] += iaz;
        P[4] += ind * bx; P[5] += ind * by; P[6] += ind * bz;
        P[7]  += iax * bx; P[8]  += iax * by; P[9]  += iax * bz;
        P[10] += iay * bx; P[11] += iay * by; P[12] += iay * bz;
        P[13] += iaz * bx; P[14] += iaz * by; P[15] += iaz * bz;
    }
    // 16 parallel warp-shuffle chains (ILP), then cross-warp in double
    #pragma unroll
    for (int o = 16; o; o >>= 1) {
        #pragma unroll
        for (int i = 0; i < 16; ++i)
            P[i] += __shfl_xor_sync(0xffffffffu, P[i], o);
    }
    if (lane == 0) {
        #pragma unroll
        for (int i = 0; i < 16; ++i) smD[w][i] = (double)P[i];
    }
    __syncthreads();

    if (tid == 0) {
        double S[16];
        #pragma unroll
        for (int i = 0; i < 16; ++i) {
            double s = 0.0;
            #pragma unroll
            for (int ww = 0; ww < 16; ++ww) s += smD[ww][i];
            S[i] = s;
        }

        const double sw = S[0];
        const double inv_sw = 1.0 / sw;
        float c1v[3] = {(float)(S[1] * inv_sw), (float)(S[2] * inv_sw), (float)(S[3] * inv_sw)};
        float c2v[3] = {(float)(S[4] * inv_sw), (float)(S[5] * inv_sw), (float)(S[6] * inv_sw)};
        // H = M - s1 s2^T / sw  (indexor saturates to {0,1} -> ind^2 == ind)
        float H[3][3];
        #pragma unroll
        for (int i = 0; i < 3; ++i)
            #pragma unroll
            for (int j = 0; j < 3; ++j)
                H[i][j] = (float)(S[7 + i * 3 + j] - S[1 + i] * S[4 + j] * inv_sw);

        // G = H^T H, Jacobi -> V, ev
        float G[3][3];
        #pragma unroll
        for (int i = 0; i < 3; ++i)
            #pragma unroll
            for (int j = 0; j < 3; ++j)
                G[i][j] = H[0][i] * H[0][j] + H[1][i] * H[1][j] + H[2][i] * H[2][j];
        float V[3][3] = {{1, 0, 0}, {0, 1, 0}, {0, 0, 1}};
        const int PP[3] = {0, 0, 1}, QQ[3] = {1, 2, 2};
        #pragma unroll
        for (int it = 0; it < 18; ++it) {
            int p = PP[it % 3], q = QQ[it % 3];
            float apq = G[p][q];
            if (fabsf(apq) > 1e-25f) {
                float theta = (G[q][q] - G[p][p]) / (2.0f * apq);
                float t = copysignf(1.0f, theta) / (fabsf(theta) + sqrtf(theta * theta + 1.0f));
                float c = rsqrtf(t * t + 1.0f);
                float sn = t * c;
                #pragma unroll
                for (int k = 0; k < 3; ++k) {
                    float gkp = G[k][p], gkq = G[k][q];
                    G[k][p] = c * gkp - sn * gkq;
                    G[k][q] = sn * gkp + c * gkq;
                }
                #pragma unroll
                for (int k = 0; k < 3; ++k) {
                    float gpk = G[p][k], gqk = G[q][k];
                    G[p][k] = c * gpk - sn * gqk;
                    G[q][k] = sn * gpk + c * gqk;
                }
                #pragma unroll
                for (int k = 0; k < 3; ++k) {
                    float vkp = V[k][p], vkq = V[k][q];
                    V[k][p] = c * vkp - sn * vkq;
                    V[k][q] = sn * vkp + c * vkq;
                }
            }
        }
        float ev[3] = {G[0][0], G[1][1], G[2][2]};
        #pragma unroll
        for (int a = 0; a < 2; ++a)
            #pragma unroll
            for (int bc = 1; bc < 3; ++bc)
                if (bc > a && ev[bc] > ev[a]) {
                    float te = ev[a]; ev[a] = ev[bc]; ev[bc] = te;
                    #pragma unroll
                    for (int k = 0; k < 3; ++k) {
                        float tv = V[k][a]; V[k][a] = V[k][bc]; V[k][bc] = tv;
                    }
                }
        float U[3][3];
        #pragma unroll
        for (int j = 0; j < 3; ++j) {
            float sig = sqrtf(fmaxf(ev[j], 0.f));
            float inv = (sig > 1e-20f) ? (1.0f / sig) : 0.f;
            #pragma unroll
            for (int i = 0; i < 3; ++i)
                U[i][j] = (H[i][0] * V[0][j] + H[i][1] * V[1][j] + H[i][2] * V[2][j]) * inv;
        }
        auto det3 = [](float M[3][3]) {
            return M[0][0] * (M[1][1] * M[2][2] - M[1][2] * M[2][1])
                 - M[0][1] * (M[1][0] * M[2][2] - M[1][2] * M[2][0])
                 + M[0][2] * (M[1][0] * M[2][1] - M[1][1] * M[2][0]);
        };
        float sign = (det3(U) * det3(V) < 0.f) ? -1.f : 1.f;
        V[0][2] *= sign; V[1][2] *= sign; V[2][2] *= sign;
        float R[3][3];
        #pragma unroll
        for (int i = 0; i < 3; ++i)
            #pragma unroll
            for (int j = 0; j < 3; ++j)
                R[i][j] = V[i][0] * U[j][0] + V[i][1] * U[j][1] + V[i][2] * U[j][2];
        float tt[3];
        #pragma unroll
        for (int i = 0; i < 3; ++i)
            tt[i] = c2v[i] - (R[i][0] * c1v[0] + R[i][1] * c1v[1] + R[i][2] * c1v[2]);

        float* T = out + b * 16;
        #pragma unroll
        for (int i = 0; i < 3; ++i) {
            T[i * 4 + 0] = R[i][0];
            T[i * 4 + 1] = R[i][1];
            T[i * 4 + 2] = R[i][2];
            T[i * 4 + 3] = tt[i];
        }
        T[12] = 0.f; T[13] = 0.f; T[14] = 0.f; T[15] = 1.f;

        auto sgn = [](float x) { return x >= 0.f ? 1.f : -1.f; };
        float qw = 0.5f * sqrtf(fmaxf(1.f + R[0][0] + R[1][1] + R[2][2], 1e-12f));
        float qx = 0.5f * sqrtf(fmaxf(1.f + R[0][0] - R[1][1] - R[2][2], 1e-12f)) * sgn(R[2][1] - R[1][2]);
        float qy = 0.5f * sqrtf(fmaxf(1.f - R[0][0] + R[1][1] - R[2][2], 1e-12f)) * sgn(R[0][2] - R[2][0]);
        float qz = 0.5f * sqrtf(fmaxf(1.f - R[0][0] - R[1][1] + R[2][2], 1e-12f)) * sgn(R[1][0] - R[0][1]);
        float* qo = out + BB * 16 + b * 4;
        qo[0] = qw; qo[1] = qx; qo[2] = qy; qo[3] = qz;
        float* to = out + BB * 16 + BB * 4 + b * 3;
        to[0] = tt[0]; to[1] = tt[1]; to[2] = tt[2];
    }
}

// ---------------------------------------------------------------------------
extern "C" void kernel_launch(void* const* d_in, const int* in_sizes, int n_in,
                              void* d_out, int out_size) {
    const float* pc1 = (const float*)d_in[0];
    const float* pc2 = (const float*)d_in[1];
    float* out = (float*)d_out;

    cudaFuncSetAttribute(cpnet_rows, cudaFuncAttributeMaxDynamicSharedMemorySize,
                         NN * (int)sizeof(float4));

    dim3 grid(NN / 16, BB);  // 256 x 8 CTAs, 16 rows each (2 per warp)
    cpnet_rows<<<grid, 256, NN * sizeof(float4)>>>(pc1, pc2);
    cpnet_finalize<<<BB, FTH>>>(pc1, out);
}

// round 4
// speedup vs baseline: 2.5090x; 1.2593x over previous
#include <cuda_runtime.h>
#include <math.h>
#include <float.h>

#define BB 8
#define NN 4096
#define NP (NN / 2)  // element pairs

static __device__ __constant__ float kEPS = 1e-5f;
static __device__ __constant__ float kF2  = 2.8853900817779268f; // FACT * log2(e)
#define SKIP_LOG2 35.0f

// Scratch (device globals; no allocation allowed)
__device__ float  g_pcn[BB][3][NN];
__device__ float  g_dist[BB][NN];
__device__ double g_dsum[BB];
__device__ double g_mom[BB][16];

typedef unsigned long long u64;

__device__ __forceinline__ float frcp(float x) {
    float r; asm("rcp.approx.f32 %0, %1;" : "=f"(r) : "f"(x)); return r;
}
__device__ __forceinline__ float fex2(float x) {
    float r; asm("ex2.approx.f32 %0, %1;" : "=f"(r) : "f"(x)); return r;
}
__device__ __forceinline__ u64 pk2(float lo, float hi) {
    u64 r; asm("mov.b64 %0, {%1, %2};" : "=l"(r) : "f"(lo), "f"(hi)); return r;
}
__device__ __forceinline__ void upk2(u64 v, float& lo, float& hi) {
    asm("mov.b64 {%0, %1}, %2;" : "=f"(lo), "=f"(hi) : "l"(v));
}
__device__ __forceinline__ u64 fma2(u64 a, u64 b, u64 c) {
    u64 d; asm("fma.rn.f32x2 %0, %1, %2, %3;" : "=l"(d) : "l"(a), "l"(b), "l"(c)); return d;
}
__device__ __forceinline__ u64 add2(u64 a, u64 b) {
    u64 d; asm("add.rn.f32x2 %0, %1, %2;" : "=l"(d) : "l"(a), "l"(b)); return d;
}

// ---------------------------------------------------------------------------
// Kernel 0: zero the double accumulators (graph replays need fresh state)
// ---------------------------------------------------------------------------
__global__ void cpnet_init() {
    int t = threadIdx.x;
    if (t < BB) g_dsum[t] = 0.0;
    if (t < BB * 16) ((double*)g_mom)[t] = 0.0;
}

// ---------------------------------------------------------------------------
// Kernel 1: rows. 4 rows per warp, 32 rows per CTA.
// SMEM: sXY[p] = {pk2(x0,x1), pk2(y0,y1)}, sZR[p] = {pk2(z0,z1), pk2(r0,r1)}
// Pass 2 uses a warp-uniform vote to skip iterations whose softmax weights
// are all below 2^-SKIP_LOG2 (softmax is extremely peaked here).
// ---------------------------------------------------------------------------
__global__ void __launch_bounds__(256)
cpnet_rows(const float* __restrict__ pc1, const float* __restrict__ pc2) {
    extern __shared__ ulonglong2 smem[];
    ulonglong2* sXY = smem;        // 2048 * 16B = 32KB
    ulonglong2* sZR = smem + NP;   // 32KB
    const int b = blockIdx.y;
    const float* p2 = pc2 + (size_t)b * 4 * NN;
    const float* p1 = pc1 + (size_t)b * 4 * NN;

    {
        const float2* px = (const float2*)p2;
        const float2* py = (const float2*)(p2 + NN);
        const float2* pz = (const float2*)(p2 + 2 * NN);
        for (int i = threadIdx.x; i < NP; i += blockDim.x) {
            float2 x = px[i], y = py[i], z = pz[i];
            float r0 = fmaf(z.x, z.x, fmaf(y.x, y.x, x.x * x.x));
            float r1 = fmaf(z.y, z.y, fmaf(y.y, y.y, x.y * x.y));
            sXY[i] = make_ulonglong2(pk2(x.x, x.y), pk2(y.x, y.y));
            sZR[i] = make_ulonglong2(pk2(z.x, z.y), pk2(r0, r1));
        }
    }
    __syncthreads();

    const int warp = threadIdx.x >> 5;
    const int lane = threadIdx.x & 31;
    const int n0 = (blockIdx.x << 5) + (warp << 2);  // 4 consecutive rows

    float qx[4], qy[4], qz[4], qr[4];
    u64 nx2[4], ny2[4], nz2[4], rp2[4];
    #pragma unroll
    for (int r = 0; r < 4; ++r) {
        qx[r] = p1[n0 + r];
        qy[r] = p1[NN + n0 + r];
        qz[r] = p1[2 * NN + n0 + r];
        qr[r] = fmaf(qz[r], qz[r], fmaf(qy[r], qy[r], qx[r] * qx[r]));
        nx2[r] = pk2(-2.f * qx[r], -2.f * qx[r]);
        ny2[r] = pk2(-2.f * qy[r], -2.f * qy[r]);
        nz2[r] = pk2(-2.f * qz[r], -2.f * qz[r]);
        rp2[r] = pk2(qr[r], qr[r]);
    }

    // ---- Pass 1: min squared distance per row ----
    float dm[4] = {FLT_MAX, FLT_MAX, FLT_MAX, FLT_MAX};
    #pragma unroll 4
    for (int p = lane; p < NP; p += 32) {
        ulonglong2 xy = sXY[p];
        ulonglong2 zr = sZR[p];
        #pragma unroll
        for (int r = 0; r < 4; ++r) {
            u64 d = fma2(nz2[r], zr.x, fma2(ny2[r], xy.y,
                         fma2(nx2[r], xy.x, add2(zr.y, rp2[r]))));
            float lo, hi; upk2(d, lo, hi);
            dm[r] = fminf(dm[r], fminf(lo, hi));
        }
    }
    #pragma unroll
    for (int o = 16; o; o >>= 1)
        #pragma unroll
        for (int r = 0; r < 4; ++r)
            dm[r] = fminf(dm[r], __shfl_xor_sync(0xffffffffu, dm[r], o));

    float cc[4], thr[4];
    u64 nc2[4];
    #pragma unroll
    for (int r = 0; r < 4; ++r) {
        cc[r] = kF2 * frcp(fmaxf(dm[r], kEPS));
        nc2[r] = pk2(-cc[r], -cc[r]);
        thr[r] = (cc[r] > SKIP_LOG2) ? kF2 * frcp(cc[r] - SKIP_LOG2) : FLT_MAX;
    }
    const u64 F2p = pk2(kF2, kF2);

    // ---- Pass 2: weights + accumulation with vote-skip ----
    u64 Zk[4] = {0, 0, 0, 0}, ax[4] = {0, 0, 0, 0};
    u64 ay[4] = {0, 0, 0, 0}, az[4] = {0, 0, 0, 0};
    for (int p = lane; p < NP; p += 32) {
        ulonglong2 xy = sXY[p];
        ulonglong2 zr = sZR[p];
        float dlo[4], dhi[4];
        bool f = false;
        #pragma unroll
        for (int r = 0; r < 4; ++r) {
            u64 d = fma2(nz2[r], zr.x, fma2(ny2[r], xy.y,
                         fma2(nx2[r], xy.x, add2(zr.y, rp2[r]))));
            upk2(d, dlo[r], dhi[r]);
            f |= (fminf(dlo[r], dhi[r]) <= thr[r]);
        }
        if (__any_sync(0xffffffffu, f)) {
            #pragma unroll
            for (int r = 0; r < 4; ++r) {
                float i0 = frcp(fmaxf(dlo[r], kEPS));
                float i1 = frcp(fmaxf(dhi[r], kEPS));
                u64 arg = fma2(pk2(i0, i1), F2p, nc2[r]);
                float g0, g1; upk2(arg, g0, g1);
                u64 w = pk2(fex2(g0), fex2(g1));
                Zk[r] = add2(Zk[r], w);
                ax[r] = fma2(w, xy.x, ax[r]);
                ay[r] = fma2(w, xy.y, ay[r]);
                az[r] = fma2(w, zr.x, az[r]);
            }
        }
    }

    float Zs[4], vx[4], vy[4], vz[4];
    #pragma unroll
    for (int r = 0; r < 4; ++r) {
        float lo, hi;
        upk2(Zk[r], lo, hi); Zs[r] = lo + hi;
        upk2(ax[r], lo, hi); vx[r] = lo + hi;
        upk2(ay[r], lo, hi); vy[r] = lo + hi;
        upk2(az[r], lo, hi); vz[r] = lo + hi;
    }
    #pragma unroll
    for (int o = 16; o; o >>= 1) {
        #pragma unroll
        for (int r = 0; r < 4; ++r) {
            Zs[r] += __shfl_xor_sync(0xffffffffu, Zs[r], o);
            vx[r] += __shfl_xor_sync(0xffffffffu, vx[r], o);
            vy[r] += __shfl_xor_sync(0xffffffffu, vy[r], o);
            vz[r] += __shfl_xor_sync(0xffffffffu, vz[r], o);
        }
    }

    if (lane == 0) {
        float dsum = 0.f;
        #pragma unroll
        for (int r = 0; r < 4; ++r) {
            float rz = 1.0f / Zs[r];
            float q0 = vx[r] * rz, q1 = vy[r] * rz, q2 = vz[r] * rz;
            float dx = qx[r] - q0, dy = qy[r] - q1, dz = qz[r] - q2;
            float dist = sqrtf(dx * dx + dy * dy + dz * dz);
            g_pcn[b][0][n0 + r] = q0;
            g_pcn[b][1][n0 + r] = q1;
            g_pcn[b][2][n0 + r] = q2;
            g_dist[b][n0 + r] = dist;
            dsum += dist;
        }
        atomicAdd(&g_dsum[b], (double)dsum);
    }
}

// ---------------------------------------------------------------------------
// Kernel 2: moments. grid (8 slices, BB batches), 256 threads, 512 elems/CTA.
// 16 uncentered moments -> double atomicAdd into g_mom.
// ---------------------------------------------------------------------------
__global__ void __launch_bounds__(256)
cpnet_moments(const float* __restrict__ pc1) {
    const int b = blockIdx.y;
    const int base = blockIdx.x * 512;
    const float* p1 = pc1 + (size_t)b * 4 * NN;
    const int tid = threadIdx.x;
    const int lane = tid & 31;
    const int w = tid >> 5;

    const float mean = (float)(g_dsum[b] * (1.0 / (double)NN));

    float P[16];
    #pragma unroll
    for (int i = 0; i < 16; ++i) P[i] = 0.f;
    #pragma unroll
    for (int k = 0; k < 2; ++k) {
        int n = base + k * 256 + tid;
        float dist = g_dist[b][n];
        float z = (dist - mean - kEPS) * 1e10f;
        float ind = 1.0f / (1.0f + __expf(z));
        float axx = p1[n], ayy = p1[NN + n], azz = p1[2 * NN + n];
        float bx = g_pcn[b][0][n], by = g_pcn[b][1][n], bz = g_pcn[b][2][n];
        float iax = ind * axx, iay = ind * ayy, iaz = ind * azz;
        P[0] += ind;
        P[1] += iax; P[2] += iay; P[3] += iaz;
        P[4] += ind * bx; P[5] += ind * by; P[6] += ind * bz;
        P[7]  += iax * bx; P[8]  += iax * by; P[9]  += iax * bz;
        P[10] += iay * bx; P[11] += iay * by; P[12] += iay * bz;
        P[13] += iaz * bx; P[14] += iaz * by; P[15] += iaz * bz;
    }
    #pragma unroll
    for (int o = 16; o; o >>= 1)
        #pragma unroll
        for (int i = 0; i < 16; ++i)
            P[i] += __shfl_xor_sync(0xffffffffu, P[i], o);

    __shared__ float sm[8][16];
    if (lane == 0) {
        #pragma unroll
        for (int i = 0; i < 16; ++i) sm[w][i] = P[i];
    }
    __syncthreads();
    if (w == 0 && lane < 16) {
        double s = 0.0;
        #pragma unroll
        for (int ww = 0; ww < 8; ++ww) s += (double)sm[ww][lane];
        atomicAdd(&g_mom[b][lane], s);
    }
}

// ---------------------------------------------------------------------------
// Kernel 3: per-batch SVD tail (fp32 + MUFU), grid BB, one thread works.
// ---------------------------------------------------------------------------
__global__ void cpnet_svd(float* __restrict__ out) {
    const int b = blockIdx.x;
    if (threadIdx.x != 0) return;

    double S[16];
    #pragma unroll
    for (int i = 0; i < 16; ++i) S[i] = g_mom[b][i];

    const double sw = S[0];
    const double inv_sw = 1.0 / sw;
    float c1v[3] = {(float)(S[1] * inv_sw), (float)(S[2] * inv_sw), (float)(S[3] * inv_sw)};
    float c2v[3] = {(float)(S[4] * inv_sw), (float)(S[5] * inv_sw), (float)(S[6] * inv_sw)};
    float H[3][3];
    #pragma unroll
    for (int i = 0; i < 3; ++i)
        #pragma unroll
        for (int j = 0; j < 3; ++j)
            H[i][j] = (float)(S[7 + i * 3 + j] - S[1 + i] * S[4 + j] * inv_sw);

    float G[3][3];
    #pragma unroll
    for (int i = 0; i < 3; ++i)
        #pragma unroll
        for (int j = 0; j < 3; ++j)
            G[i][j] = H[0][i] * H[0][j] + H[1][i] * H[1][j] + H[2][i] * H[2][j];
    float V[3][3] = {{1, 0, 0}, {0, 1, 0}, {0, 0, 1}};
    const int PP[3] = {0, 0, 1}, QQ[3] = {1, 2, 2};
    #pragma unroll
    for (int it = 0; it < 18; ++it) {
        int p = PP[it % 3], q = QQ[it % 3];
        float apq = G[p][q];
        if (fabsf(apq) > 1e-25f) {
            float theta = (G[q][q] - G[p][p]) / (2.0f * apq);
            float t = copysignf(1.0f, theta) / (fabsf(theta) + sqrtf(theta * theta + 1.0f));
            float c = rsqrtf(t * t + 1.0f);
            float sn = t * c;
            #pragma unroll
            for (int k = 0; k < 3; ++k) {
                float gkp = G[k][p], gkq = G[k][q];
                G[k][p] = c * gkp - sn * gkq;
                G[k][q] = sn * gkp + c * gkq;
            }
            #pragma unroll
            for (int k = 0; k < 3; ++k) {
                float gpk = G[p][k], gqk = G[q][k];
                G[p][k] = c * gpk - sn * gqk;
                G[q][k] = sn * gpk + c * gqk;
            }
            #pragma unroll
            for (int k = 0; k < 3; ++k) {
                float vkp = V[k][p], vkq = V[k][q];
                V[k][p] = c * vkp - sn * vkq;
                V[k][q] = sn * vkp + c * vkq;
            }
        }
    }
    float ev[3] = {G[0][0], G[1][1], G[2][2]};
    #pragma unroll
    for (int a = 0; a < 2; ++a)
        #pragma unroll
        for (int bc = 1; bc < 3; ++bc)
            if (bc > a && ev[bc] > ev[a]) {
                float te = ev[a]; ev[a] = ev[bc]; ev[bc] = te;
                #pragma unroll
                for (int k = 0; k < 3; ++k) {
                    float tv = V[k][a]; V[k][a] = V[k][bc]; V[k][bc] = tv;
                }
            }
    float U[3][3];
    #pragma unroll
    for (int j = 0; j < 3; ++j) {
        float sig = sqrtf(fmaxf(ev[j], 0.f));
        float inv = (sig > 1e-20f) ? (1.0f / sig) : 0.f;
        #pragma unroll
        for (int i = 0; i < 3; ++i)
            U[i][j] = (H[i][0] * V[0][j] + H[i][1] * V[1][j] + H[i][2] * V[2][j]) * inv;
    }
    auto det3 = [](float M[3][3]) {
        return M[0][0] * (M[1][1] * M[2][2] - M[1][2] * M[2][1])
             - M[0][1] * (M[1][0] * M[2][2] - M[1][2] * M[2][0])
             + M[0][2] * (M[1][0] * M[2][1] - M[1][1] * M[2][0]);
    };
    float sign = (det3(U) * det3(V) < 0.f) ? -1.f : 1.f;
    V[0][2] *= sign; V[1][2] *= sign; V[2][2] *= sign;
    float R[3][3];
    #pragma unroll
    for (int i = 0; i < 3; ++i)
        #pragma unroll
        for (int j = 0; j < 3; ++j)
            R[i][j] = V[i][0] * U[j][0] + V[i][1] * U[j][1] + V[i][2] * U[j][2];
    float tt[3];
    #pragma unroll
    for (int i = 0; i < 3; ++i)
        tt[i] = c2v[i] - (R[i][0] * c1v[0] + R[i][1] * c1v[1] + R[i][2] * c1v[2]);

    float* T = out + b * 16;
    #pragma unroll
    for (int i = 0; i < 3; ++i) {
        T[i * 4 + 0] = R[i][0];
        T[i * 4 + 1] = R[i][1];
        T[i * 4 + 2] = R[i][2];
        T[i * 4 + 3] = tt[i];
    }
    T[12] = 0.f; T[13] = 0.f; T[14] = 0.f; T[15] = 1.f;

    auto sgn = [](float x) { return x >= 0.f ? 1.f : -1.f; };
    float qw = 0.5f * sqrtf(fmaxf(1.f + R[0][0] + R[1][1] + R[2][2], 1e-12f));
    float qx = 0.5f * sqrtf(fmaxf(1.f + R[0][0] - R[1][1] - R[2][2], 1e-12f)) * sgn(R[2][1] - R[1][2]);
    float qy = 0.5f * sqrtf(fmaxf(1.f - R[0][0] + R[1][1] - R[2][2], 1e-12f)) * sgn(R[0][2] - R[2][0]);
    float qz = 0.5f * sqrtf(fmaxf(1.f - R[0][0] - R[1][1] + R[2][2], 1e-12f)) * sgn(R[1][0] - R[0][1]);
    float* qo = out + BB * 16 + b * 4;
    qo[0] = qw; qo[1] = qx; qo[2] = qy; qo[3] = qz;
    float* to = out + BB * 16 + BB * 4 + b * 3;
    to[0] = tt[0]; to[1] = tt[1]; to[2] = tt[2];
}

// ---------------------------------------------------------------------------
extern "C" void kernel_launch(void* const* d_in, const int* in_sizes, int n_in,
                              void* d_out, int out_size) {
    const float* pc1 = (const float*)d_in[0];
    const float* pc2 = (const float*)d_in[1];
    float* out = (float*)d_out;

    cudaFuncSetAttribute(cpnet_rows, cudaFuncAttributeMaxDynamicSharedMemorySize,
                         2 * NP * (int)sizeof(ulonglong2));

    cpnet_init<<<1, 128>>>();
    dim3 grid(NN / 32, BB);  // 128 x 8 = 1024 CTAs, 32 rows each (4 per warp)
    cpnet_rows<<<grid, 256, 2 * NP * sizeof(ulonglong2)>>>(pc1, pc2);
    dim3 mgrid(NN / 512, BB);  // 8 x 8
    cpnet_moments<<<mgrid, 256>>>(pc1);
    cpnet_svd<<<BB, 32>>>(out);
}